// round 1
// baseline (speedup 1.0000x reference)
#include <cuda_runtime.h>
#include <math.h>

#define DIMV    64
#define NEMB    512
#define TPB     128      // threads per block (main kernel)
#define ROWS    8        // rows processed per chunk
#define NWARP   (TPB/32)
#define CODESPT (NEMB/TPB)   // 4 codes per thread

// ---- device scratch (no allocations allowed) ----
__device__ float g_counts[NEMB];
__device__ float g_embed_sum[DIMV * NEMB];
__device__ float g_wsq[NEMB];
__device__ float g_loss_sum;

// monotone order-preserving map float -> uint (for min via unsigned compare)
__device__ __forceinline__ unsigned ford(float f) {
    unsigned u = __float_as_uint(f);
    return (u & 0x80000000u) ? ~u : (u | 0x80000000u);
}
__device__ __forceinline__ float ford_inv(unsigned m) {
    unsigned u = (m & 0x80000000u) ? (m ^ 0x80000000u) : ~m;
    return __uint_as_float(u);
}

// ---------------------------------------------------------------------------
// Kernel 1: zero scratch + precompute ||w_j||^2
// ---------------------------------------------------------------------------
__global__ void vq_init(const float* __restrict__ w) {
    int tid = blockIdx.x * blockDim.x + threadIdx.x;
    if (tid < DIMV * NEMB) g_embed_sum[tid] = 0.0f;
    if (tid < NEMB) {
        g_counts[tid] = 0.0f;
        float s = 0.0f;
#pragma unroll
        for (int k = 0; k < DIMV; k++) {
            float v = w[k * NEMB + tid];
            s = fmaf(v, v, s);
        }
        g_wsq[tid] = s;
    }
    if (tid == 0) g_loss_sum = 0.0f;
}

// ---------------------------------------------------------------------------
// Kernel 2: main — distances, argmin, scatter-accumulate counts/embed_sum/loss
// smem layout (floats):
//   sw   [0, 32768)      : w tile [64][512]
//   swsq [32768, 33280)  : ||w_j||^2
//   sx   [33280, 33792)  : 8 rows x 64
//   sred [33792, 33856)  : 32 x u64 warp-argmin results (8B aligned)
//   sxsq [33856, 33864)  : per-row ||x||^2
//   sloss[33864]         : block loss accumulator
//   sj   [33865, 33873)  : per-row winning code index
// total 33888 floats = 135552 bytes
// ---------------------------------------------------------------------------
#define SMEM_FLOATS 33888
#define SMEM_BYTES  (SMEM_FLOATS * 4)

__global__ __launch_bounds__(TPB, 1)
void vq_main(const float* __restrict__ inp, const float* __restrict__ w, int nrows) {
    extern __shared__ float sm[];
    float* sw   = sm;
    float* swsq = sm + DIMV * NEMB;
    float* sx   = swsq + NEMB;
    unsigned long long* sred = (unsigned long long*)(sx + ROWS * DIMV);
    float* sxsq  = (float*)(sred + ROWS * NWARP);
    float* sloss = sxsq + ROWS;
    int*   sj    = (int*)(sloss + 1);

    const int tid  = threadIdx.x;
    const int lane = tid & 31;
    const int wid  = tid >> 5;
    const int c0   = tid * CODESPT;

    // stage w into smem (float4, coalesced)
    const float4* w4 = (const float4*)w;
#pragma unroll
    for (int i = tid; i < DIMV * NEMB / 4; i += TPB)
        ((float4*)sw)[i] = w4[i];
    for (int j = tid; j < NEMB; j += TPB)
        swsq[j] = g_wsq[j];
    if (tid == 0) *sloss = 0.0f;

    const int nchunks = nrows / ROWS;
    for (int chunk = blockIdx.x; chunk < nchunks; chunk += gridDim.x) {
        if (tid < ROWS) sxsq[tid] = 0.0f;
        __syncthreads();  // S1: sxsq zeroed; prev-iter readers of sx/sj done

        // load 8 rows (512 floats) as one float4 per thread; accumulate ||x||^2
        float4 xv4 = ((const float4*)(inp + (size_t)chunk * (ROWS * DIMV)))[tid];
        ((float4*)sx)[tid] = xv4;
        float pq = fmaf(xv4.x, xv4.x, fmaf(xv4.y, xv4.y, fmaf(xv4.z, xv4.z, xv4.w * xv4.w)));
        atomicAdd(&sxsq[tid >> 4], pq);   // 16 threads per row
        __syncthreads();  // S2: sx, sxsq ready

        // ---- distance GEMM: each thread, 4 codes x 8 rows ----
        float4 acc[ROWS];
#pragma unroll
        for (int r = 0; r < ROWS; r++) acc[r] = make_float4(0.f, 0.f, 0.f, 0.f);

        const float* swp = sw + c0;
#pragma unroll 16
        for (int k = 0; k < DIMV; k++) {
            float4 wv = *(const float4*)(swp + k * NEMB);
#pragma unroll
            for (int r = 0; r < ROWS; r++) {
                float xv = sx[r * DIMV + k];
                acc[r].x = fmaf(xv, wv.x, acc[r].x);
                acc[r].y = fmaf(xv, wv.y, acc[r].y);
                acc[r].z = fmaf(xv, wv.z, acc[r].z);
                acc[r].w = fmaf(xv, wv.w, acc[r].w);
            }
        }

        // ---- per-row argmin of (||w||^2 - 2 x.w) ----
        float4 wq = *(const float4*)(swsq + c0);
#pragma unroll
        for (int r = 0; r < ROWS; r++) {
            float s0 = fmaf(-2.0f, acc[r].x, wq.x);
            float s1 = fmaf(-2.0f, acc[r].y, wq.y);
            float s2 = fmaf(-2.0f, acc[r].z, wq.z);
            float s3 = fmaf(-2.0f, acc[r].w, wq.w);
            unsigned long long key =
                ((unsigned long long)ford(s0) << 32) | (unsigned)(c0 + 0);
            unsigned long long k1 =
                ((unsigned long long)ford(s1) << 32) | (unsigned)(c0 + 1);
            unsigned long long k2 =
                ((unsigned long long)ford(s2) << 32) | (unsigned)(c0 + 2);
            unsigned long long k3 =
                ((unsigned long long)ford(s3) << 32) | (unsigned)(c0 + 3);
            if (k1 < key) key = k1;
            if (k2 < key) key = k2;
            if (k3 < key) key = k3;
#pragma unroll
            for (int off = 16; off; off >>= 1) {
                unsigned long long o = __shfl_xor_sync(0xFFFFFFFFu, key, off);
                if (o < key) key = o;
            }
            if (lane == 0) sred[r * NWARP + wid] = key;
        }
        __syncthreads();  // S3: sred ready

        if (tid < ROWS) {
            int r = tid;
            unsigned long long best = sred[r * NWARP + 0];
#pragma unroll
            for (int wi = 1; wi < NWARP; wi++) {
                unsigned long long o = sred[r * NWARP + wi];
                if (o < best) best = o;
            }
            int j = (int)(best & 0xFFFFFFFFull);
            float val = ford_inv((unsigned)(best >> 32));
            float mind = val + sxsq[r];       // full squared distance
            atomicAdd(sloss, mind);
            sj[r] = j;
            atomicAdd(&g_counts[j], 1.0f);
        }
        __syncthreads();  // S4: sj ready

        // embed_sum scatter: 512 (row,dim) pairs over 128 threads
#pragma unroll
        for (int p = tid; p < ROWS * DIMV; p += TPB) {
            int r = p >> 6;
            int k = p & 63;
            atomicAdd(&g_embed_sum[k * NEMB + sj[r]], sx[r * DIMV + k]);
        }
        // next-iter S1 protects sx/sj against overwrite
    }

    __syncthreads();
    if (tid == 0) atomicAdd(&g_loss_sum, *sloss);
}

// ---------------------------------------------------------------------------
// Kernel 3: finalize — EMA update, normalization, loss & perplexity, outputs
// out layout: [0]=loss [1]=perplexity [2..2+32768)=new_w
//             [+512)=new_cluster_size [+32768)=new_embed_avg
// ---------------------------------------------------------------------------
__global__ void vq_final(const float* __restrict__ cs_in,
                         const float* __restrict__ ea_in,
                         float* __restrict__ out, int nrows) {
    __shared__ float red[NEMB];
    int j = threadIdx.x;

    float counts = g_counts[j];
    float ncs = fmaf(0.99f, cs_in[j], 0.01f * counts);

    red[j] = ncs;
    __syncthreads();
#pragma unroll
    for (int off = NEMB / 2; off; off >>= 1) {
        if (j < off) red[j] += red[j + off];
        __syncthreads();
    }
    float n = red[0];
    __syncthreads();

    float csj = (ncs + 1e-5f) / (n + (float)NEMB * 1e-5f) * n;
    float inv = 1.0f / csj;

    out[2 + DIMV * NEMB + j] = ncs;  // new_cluster_size

    const int W_OFF  = 2;
    const int EA_OFF = 2 + DIMV * NEMB + NEMB;
#pragma unroll
    for (int k = 0; k < DIMV; k++) {
        float ea = fmaf(0.99f, ea_in[k * NEMB + j], 0.01f * g_embed_sum[k * NEMB + j]);
        out[EA_OFF + k * NEMB + j] = ea;
        out[W_OFF  + k * NEMB + j] = ea * inv;
    }

    // perplexity
    float p = counts / (float)nrows;
    red[j] = p * logf(p + 1e-10f);
    __syncthreads();
#pragma unroll
    for (int off = NEMB / 2; off; off >>= 1) {
        if (j < off) red[j] += red[j + off];
        __syncthreads();
    }
    if (j == 0) {
        out[1] = expf(-red[0]);
        out[0] = 0.25f * g_loss_sum / ((float)nrows * (float)DIMV);
    }
}

// ---------------------------------------------------------------------------
extern "C" void kernel_launch(void* const* d_in, const int* in_sizes, int n_in,
                              void* d_out, int out_size) {
    const float* inp = (const float*)d_in[0];
    const float* w   = (const float*)d_in[1];
    const float* cs  = (const float*)d_in[2];
    const float* ea  = (const float*)d_in[3];
    int nrows = in_sizes[0] / DIMV;

    cudaFuncSetAttribute(vq_main, cudaFuncAttributeMaxDynamicSharedMemorySize, SMEM_BYTES);

    vq_init<<<64, 512>>>(w);
    vq_main<<<148, TPB, SMEM_BYTES>>>(inp, w, nrows);
    vq_final<<<1, NEMB>>>(cs, ea, (float*)d_out, nrows);
}

// round 3
// speedup vs baseline: 3.1498x; 3.1498x over previous
#include <cuda_runtime.h>
#include <cuda_bf16.h>
#include <math.h>

#define DIMV   64
#define NEMB   512
#define TPB    128
#define TILE_M 128
#define ROWB   144          // padded row stride: 72 bf16 (conflict-free ldmatrix)

// ---------------- smem layout (bytes) ----------------
#define B_HI_OFF   0                          // 512 x 144B
#define B_LO_OFF   (512*ROWB)                 // 73728
#define A_HI_OFF   (2*512*ROWB)               // 147456, 128 x 144B
#define A_LO_OFF   (A_HI_OFF + 128*ROWB)      // 165888
#define SWSQ_OFF   (A_LO_OFF + 128*ROWB)      // 184320, 512 f32
#define SCNT_OFF   (SWSQ_OFF + 2048)          // 512 f32
#define SXSQ_OFF   (SCNT_OFF + 2048)          // 128 f32
#define SJ_OFF     (SXSQ_OFF + 512)           // 128 i32
#define SLOSS_OFF  (SJ_OFF + 512)
#define SMEM_BYTES (SLOSS_OFF + 16)           // 189472

// ---------------- device scratch ----------------
__device__ float          g_wsq[NEMB];
__device__ unsigned short g_w_hi[NEMB * DIMV];   // [j][k], w' = -2w, bf16 hi
__device__ unsigned short g_w_lo[NEMB * DIMV];   // bf16 residual
__device__ __align__(16) float g_embed_sum[NEMB * DIMV];  // code-major [j][k]
__device__ float          g_counts[NEMB];
__device__ float          g_loss_sum;

// ---------------- helpers ----------------
__device__ __forceinline__ unsigned smem_u32(const void* p) {
    unsigned a;
    asm("{ .reg .u64 t; cvta.to.shared.u64 t, %1; cvt.u32.u64 %0, t; }" : "=r"(a) : "l"(p));
    return a;
}
__device__ __forceinline__ unsigned bfbits(float f) {
    return (unsigned)__bfloat16_as_ushort(__float2bfloat16(f));
}
__device__ __forceinline__ float bflo(unsigned u) { return __uint_as_float(u << 16); }
__device__ __forceinline__ float bfhi(unsigned u) { return __uint_as_float(u & 0xFFFF0000u); }

__device__ __forceinline__ void ldm_x4(unsigned &r0, unsigned &r1, unsigned &r2, unsigned &r3,
                                       unsigned addr) {
    asm volatile("ldmatrix.sync.aligned.m8n8.x4.shared.b16 {%0,%1,%2,%3}, [%4];"
                 : "=r"(r0), "=r"(r1), "=r"(r2), "=r"(r3) : "r"(addr));
}
__device__ __forceinline__ void mma_bf16(float* d, const unsigned* a, unsigned b0, unsigned b1) {
    asm volatile("mma.sync.aligned.m16n8k16.row.col.f32.bf16.bf16.f32 "
                 "{%0,%1,%2,%3},{%4,%5,%6,%7},{%8,%9},{%0,%1,%2,%3};"
                 : "+f"(d[0]), "+f"(d[1]), "+f"(d[2]), "+f"(d[3])
                 : "r"(a[0]), "r"(a[1]), "r"(a[2]), "r"(a[3]), "r"(b0), "r"(b1));
}
__device__ __forceinline__ void red_add_v4(float* p, float a, float b, float c, float d) {
    asm volatile("red.global.add.v4.f32 [%0], {%1,%2,%3,%4};"
                 :: "l"(p), "f"(a), "f"(b), "f"(c), "f"(d) : "memory");
}

// ---------------------------------------------------------------------------
// Kernel 1: zero scratch, ||w||^2, build w' = -2w bf16 hi/lo (code-major)
// ---------------------------------------------------------------------------
__global__ void vq_init(const float* __restrict__ w) {
    int gid = blockIdx.x * blockDim.x + threadIdx.x;
    if (gid < NEMB * DIMV) g_embed_sum[gid] = 0.0f;
    if (gid < NEMB) {
        int j = gid;
        float s = 0.0f;
#pragma unroll
        for (int k = 0; k < DIMV; k++) {
            float v = w[k * NEMB + j];
            s = fmaf(v, v, s);
            float m = -2.0f * v;
            unsigned h = bfbits(m);
            float r = m - bflo(h);
            g_w_hi[j * DIMV + k] = (unsigned short)h;
            g_w_lo[j * DIMV + k] = (unsigned short)bfbits(r);
        }
        g_wsq[j] = s;
        g_counts[j] = 0.0f;
    }
    if (gid == 0) g_loss_sum = 0.0f;
}

// ---------------------------------------------------------------------------
// Kernel 2: persistent main — bf16-split HMMA GEMM + fused argmin + scatter
// ---------------------------------------------------------------------------
__global__ __launch_bounds__(TPB, 1)
void vq_main(const float* __restrict__ inp, int nrows) {
    extern __shared__ __align__(1024) char sm[];
    const unsigned sbase = smem_u32(sm);
    const int tid  = threadIdx.x;
    const int lane = tid & 31;
    const int wid  = tid >> 5;

    float* swsq  = (float*)(sm + SWSQ_OFF);
    float* scnt  = (float*)(sm + SCNT_OFF);
    float* sxsq  = (float*)(sm + SXSQ_OFF);
    int*   sj    = (int*)(sm + SJ_OFF);
    float* sloss = (float*)(sm + SLOSS_OFF);

    // --- stage B (w' hi/lo) into padded rows + swsq + zero counters ---
    {
        const uint4* srcH = (const uint4*)g_w_hi;
        const uint4* srcL = (const uint4*)g_w_lo;
#pragma unroll
        for (int i = 0; i < 32; i++) {
            int idx = tid + i * TPB;        // 0..4095 : 16B chunk index
            int row = idx >> 3, c = idx & 7;
            *(uint4*)(sm + B_HI_OFF + row * ROWB + c * 16) = srcH[idx];
            *(uint4*)(sm + B_LO_OFF + row * ROWB + c * 16) = srcL[idx];
        }
        for (int j = tid; j < NEMB; j += TPB) { swsq[j] = g_wsq[j]; scnt[j] = 0.0f; }
        if (tid == 0) *sloss = 0.0f;
    }

    // lane-fixed ldmatrix address offsets
    const unsigned aoff = (unsigned)((lane & 15) * ROWB + (lane >> 4) * 16);
    const unsigned boff = (unsigned)(((lane & 7) + ((lane >> 4) << 3)) * ROWB + ((lane >> 3) & 1) * 16);
    const unsigned aHbase = sbase + A_HI_OFF + (unsigned)(wid * 32 * ROWB) + aoff;
    const unsigned aLbase = sbase + A_LO_OFF + (unsigned)(wid * 32 * ROWB) + aoff;
    const unsigned bHbase = sbase + B_HI_OFF + boff;
    const unsigned bLbase = sbase + B_LO_OFF + boff;

    float loss_acc = 0.0f;
    const int nchunks = nrows / TILE_M;

    for (int tile = blockIdx.x; tile < nchunks; tile += gridDim.x) {
        __syncthreads();   // S1: previous scatter done; A smem reusable

        // ---- load + convert x tile (128 x 64 fp32, coalesced) ----
        const float4* src = (const float4*)inp + (size_t)tile * (TILE_M * DIMV / 4);
#pragma unroll
        for (int i = 0; i < 16; i++) {
            int idx = tid + (i << 7);
            float4 v = __ldg(src + idx);
            unsigned h0 = bfbits(v.x), h1 = bfbits(v.y), h2 = bfbits(v.z), h3 = bfbits(v.w);
            unsigned l0 = bfbits(v.x - bflo(h0)), l1 = bfbits(v.y - bflo(h1));
            unsigned l2 = bfbits(v.z - bflo(h2)), l3 = bfbits(v.w - bflo(h3));
            unsigned long long hw = ((unsigned long long)(h2 | (h3 << 16)) << 32) | (h0 | (h1 << 16));
            unsigned long long lw = ((unsigned long long)(l2 | (l3 << 16)) << 32) | (l0 | (l1 << 16));
            int row = idx >> 4, kc = idx & 15;
            *(unsigned long long*)(sm + A_HI_OFF + row * ROWB + kc * 8) = hw;
            *(unsigned long long*)(sm + A_LO_OFF + row * ROWB + kc * 8) = lw;
            float pq = fmaf(v.x, v.x, fmaf(v.y, v.y, fmaf(v.z, v.z, v.w * v.w)));
#pragma unroll
            for (int m = 1; m < 16; m <<= 1) pq += __shfl_xor_sync(0xFFFFFFFFu, pq, m);
            if ((lane & 15) == 0) sxsq[(i << 3) + (tid >> 4)] = pq;
        }
        __syncthreads();   // S2: A smem + sxsq ready

        // ---- load A fragments (resident for whole tile) ----
        unsigned Ah[2][4][4], Al[2][4][4];
#pragma unroll
        for (int mt = 0; mt < 2; mt++)
#pragma unroll
            for (int ks = 0; ks < 4; ks++) {
                unsigned ao = (unsigned)(mt * 16 * ROWB + ks * 32);
                ldm_x4(Ah[mt][ks][0], Ah[mt][ks][1], Ah[mt][ks][2], Ah[mt][ks][3], aHbase + ao);
                ldm_x4(Al[mt][ks][0], Al[mt][ks][1], Al[mt][ks][2], Al[mt][ks][3], aLbase + ao);
            }

        float bst[4] = {__int_as_float(0x7F800000), __int_as_float(0x7F800000),
                        __int_as_float(0x7F800000), __int_as_float(0x7F800000)};
        int   bj[4]  = {0, 0, 0, 0};

        for (int chunk = 0; chunk < 8; chunk++) {
            float acc[2][8][4];
#pragma unroll
            for (int mt = 0; mt < 2; mt++)
#pragma unroll
                for (int nt = 0; nt < 8; nt++)
#pragma unroll
                    for (int q = 0; q < 4; q++) acc[mt][nt][q] = 0.0f;

            unsigned bc = (unsigned)(chunk * 64 * ROWB);
#pragma unroll
            for (int ks = 0; ks < 4; ks++)
#pragma unroll
                for (int pr = 0; pr < 4; pr++) {
                    unsigned off = bc + (unsigned)(pr * 16 * ROWB + ks * 32);
                    unsigned h0, h1, h2, h3, L0, L1, L2, L3;
                    ldm_x4(h0, h1, h2, h3, bHbase + off);
                    ldm_x4(L0, L1, L2, L3, bLbase + off);
#pragma unroll
                    for (int mt = 0; mt < 2; mt++) {
                        mma_bf16(acc[mt][2*pr],   Ah[mt][ks], h0, h1);
                        mma_bf16(acc[mt][2*pr+1], Ah[mt][ks], h2, h3);
                        mma_bf16(acc[mt][2*pr],   Ah[mt][ks], L0, L1);
                        mma_bf16(acc[mt][2*pr+1], Ah[mt][ks], L2, L3);
                        mma_bf16(acc[mt][2*pr],   Al[mt][ks], h0, h1);
                        mma_bf16(acc[mt][2*pr+1], Al[mt][ks], h2, h3);
                    }
                }

            // ---- fold into per-row running argmin (ascending j scan) ----
#pragma unroll
            for (int nt = 0; nt < 8; nt++) {
                int jb = chunk * 64 + nt * 8 + (lane & 3) * 2;
                float2 wq = *(float2*)(swsq + jb);
#pragma unroll
                for (int mt = 0; mt < 2; mt++) {
                    float s0 = acc[mt][nt][0] + wq.x;
                    float s1 = acc[mt][nt][1] + wq.y;
                    float s2 = acc[mt][nt][2] + wq.x;
                    float s3 = acc[mt][nt][3] + wq.y;
                    int slo = mt * 2, shi = mt * 2 + 1;
                    if (s0 < bst[slo]) { bst[slo] = s0; bj[slo] = jb; }
                    if (s1 < bst[slo]) { bst[slo] = s1; bj[slo] = jb + 1; }
                    if (s2 < bst[shi]) { bst[shi] = s2; bj[shi] = jb; }
                    if (s3 < bst[shi]) { bst[shi] = s3; bj[shi] = jb + 1; }
                }
            }
        }

        // ---- quad-reduce (val, idx) lexicographic; owners record results ----
#pragma unroll
        for (int s = 0; s < 4; s++) {
            float b = bst[s]; int j = bj[s];
#pragma unroll
            for (int off = 1; off <= 2; off <<= 1) {
                float ob = __shfl_xor_sync(0xFFFFFFFFu, b, off);
                int   oj = __shfl_xor_sync(0xFFFFFFFFu, j, off);
                if (ob < b || (ob == b && oj < j)) { b = ob; j = oj; }
            }
            if ((lane & 3) == 0) {
                int r = wid * 32 + (s >> 1) * 16 + (lane >> 2) + (s & 1) * 8;
                sj[r] = j;
                loss_acc += b + sxsq[r];
                atomicAdd(&scnt[j], 1.0f);
            }
        }
        __syncthreads();   // S3: sj complete

        // ---- embed_sum scatter: one row per thread, v4 global reductions ----
        {
            int j = sj[tid];
            float* dst = g_embed_sum + j * DIMV;
            const char* hrow = sm + A_HI_OFF + tid * ROWB;
            const char* lrow = sm + A_LO_OFF + tid * ROWB;
#pragma unroll
            for (int c = 0; c < 8; c++) {
                uint4 h = *(const uint4*)(hrow + c * 16);
                uint4 l = *(const uint4*)(lrow + c * 16);
                float f0 = bflo(h.x) + bflo(l.x), f1 = bfhi(h.x) + bfhi(l.x);
                float f2 = bflo(h.y) + bflo(l.y), f3 = bfhi(h.y) + bfhi(l.y);
                float f4 = bflo(h.z) + bflo(l.z), f5 = bfhi(h.z) + bfhi(l.z);
                float f6 = bflo(h.w) + bflo(l.w), f7 = bfhi(h.w) + bfhi(l.w);
                red_add_v4(dst + c * 8,     f0, f1, f2, f3);
                red_add_v4(dst + c * 8 + 4, f4, f5, f6, f7);
            }
        }
    }

    // ---- flush block-local accumulators ----
    atomicAdd(sloss, loss_acc);
    __syncthreads();
    for (int j = tid; j < NEMB; j += TPB)
        if (scnt[j] != 0.0f) atomicAdd(&g_counts[j], scnt[j]);
    if (tid == 0) atomicAdd(&g_loss_sum, *sloss);
}

// ---------------------------------------------------------------------------
// Kernel 3: finalize — EMA update, outputs
// ---------------------------------------------------------------------------
__global__ void vq_final(const float* __restrict__ cs_in,
                         const float* __restrict__ ea_in,
                         float* __restrict__ out, int nrows) {
    __shared__ float red[NEMB];
    int j = threadIdx.x;

    float counts = g_counts[j];
    float ncs = fmaf(0.99f, cs_in[j], 0.01f * counts);

    red[j] = ncs;
    __syncthreads();
#pragma unroll
    for (int off = NEMB / 2; off; off >>= 1) {
        if (j < off) red[j] += red[j + off];
        __syncthreads();
    }
    float n = red[0];
    __syncthreads();

    float csj = (ncs + 1e-5f) / (n + (float)NEMB * 1e-5f) * n;
    float inv = 1.0f / csj;

    out[2 + DIMV * NEMB + j] = ncs;  // new_cluster_size

    const int W_OFF  = 2;
    const int EA_OFF = 2 + DIMV * NEMB + NEMB;
#pragma unroll
    for (int k = 0; k < DIMV; k++) {
        float ea = fmaf(0.99f, ea_in[k * NEMB + j], 0.01f * g_embed_sum[j * DIMV + k]);
        out[EA_OFF + k * NEMB + j] = ea;
        out[W_OFF  + k * NEMB + j] = ea * inv;
    }

    float p = counts / (float)nrows;
    red[j] = p * logf(p + 1e-10f);
    __syncthreads();
#pragma unroll
    for (int off = NEMB / 2; off; off >>= 1) {
        if (j < off) red[j] += red[j + off];
        __syncthreads();
    }
    if (j == 0) {
        out[1] = expf(-red[0]);
        out[0] = 0.25f * g_loss_sum / ((float)nrows * (float)DIMV);
    }
}

// ---------------------------------------------------------------------------
extern "C" void kernel_launch(void* const* d_in, const int* in_sizes, int n_in,
                              void* d_out, int out_size) {
    const float* inp = (const float*)d_in[0];
    const float* w   = (const float*)d_in[1];
    const float* cs  = (const float*)d_in[2];
    const float* ea  = (const float*)d_in[3];
    int nrows = in_sizes[0] / DIMV;

    cudaFuncSetAttribute(vq_main, cudaFuncAttributeMaxDynamicSharedMemorySize, SMEM_BYTES);

    vq_init<<<64, 512>>>(w);
    vq_main<<<148, TPB, SMEM_BYTES>>>(inp, nrows);
    vq_final<<<1, NEMB>>>(cs, ea, (float*)d_out, nrows);
}

// round 5
// speedup vs baseline: 3.2701x; 1.0382x over previous
#include <cuda_runtime.h>
#include <cuda_bf16.h>
#include <math.h>

#define DIMV   64
#define NEMB   512
#define TPB    128
#define TILE_M 128
#define ROWB   144          // padded row stride: 72 bf16 (conflict-free ldmatrix)

// ---------------- smem layout (bytes) ----------------
#define B_HI_OFF   0                          // 512 x 144B
#define B_LO_OFF   (512*ROWB)                 // 73728
#define A_HI_OFF   (2*512*ROWB)               // 147456, 128 x 144B
#define A_LO_OFF   (A_HI_OFF + 128*ROWB)      // 165888
#define STAGE_OFF  (A_LO_OFF + 128*ROWB)      // 184320, raw fp32 tile 32KB
#define SWSQ_OFF   (STAGE_OFF + 32768)        // 217088, 512 f32
#define SCNT_OFF   (SWSQ_OFF + 2048)          // 512 f32
#define SXSQ_OFF   (SCNT_OFF + 2048)          // 128 f32
#define SJ_OFF     (SXSQ_OFF + 512)           // 128 i32
#define SLOSS_OFF  (SJ_OFF + 512)
#define SMEM_BYTES (SLOSS_OFF + 16)           // 222240

// ---------------- device scratch ----------------
__device__ float          g_wsq[NEMB];
__device__ unsigned short g_w_hi[NEMB * DIMV];   // [j][k], w' = -2w, bf16 hi
__device__ unsigned short g_w_lo[NEMB * DIMV];   // bf16 residual
__device__ __align__(16) float g_embed_sum[NEMB * DIMV];  // code-major [j][k]
__device__ float          g_counts[NEMB];
__device__ float          g_inv[NEMB];
__device__ float          g_loss_sum;

// ---------------- helpers ----------------
__device__ __forceinline__ unsigned smem_u32(const void* p) {
    unsigned a;
    asm("{ .reg .u64 t; cvta.to.shared.u64 t, %1; cvt.u32.u64 %0, t; }" : "=r"(a) : "l"(p));
    return a;
}
__device__ __forceinline__ unsigned bfbits(float f) {
    return (unsigned)__bfloat16_as_ushort(__float2bfloat16(f));
}
__device__ __forceinline__ float bflo(unsigned u) { return __uint_as_float(u << 16); }
__device__ __forceinline__ float bfhi(unsigned u) { return __uint_as_float(u & 0xFFFF0000u); }

__device__ __forceinline__ void ldm_x4(unsigned &r0, unsigned &r1, unsigned &r2, unsigned &r3,
                                       unsigned addr) {
    asm volatile("ldmatrix.sync.aligned.m8n8.x4.shared.b16 {%0,%1,%2,%3}, [%4];"
                 : "=r"(r0), "=r"(r1), "=r"(r2), "=r"(r3) : "r"(addr));
}
__device__ __forceinline__ void mma_bf16(float* d, const unsigned* a, unsigned b0, unsigned b1) {
    asm volatile("mma.sync.aligned.m16n8k16.row.col.f32.bf16.bf16.f32 "
                 "{%0,%1,%2,%3},{%4,%5,%6,%7},{%8,%9},{%0,%1,%2,%3};"
                 : "+f"(d[0]), "+f"(d[1]), "+f"(d[2]), "+f"(d[3])
                 : "r"(a[0]), "r"(a[1]), "r"(a[2]), "r"(a[3]), "r"(b0), "r"(b1));
}
__device__ __forceinline__ void red_add_v4(float* p, float a, float b, float c, float d) {
    asm volatile("red.global.add.v4.f32 [%0], {%1,%2,%3,%4};"
                 :: "l"(p), "f"(a), "f"(b), "f"(c), "f"(d) : "memory");
}
__device__ __forceinline__ void cp_async16(unsigned dst, const void* src) {
    asm volatile("cp.async.cg.shared.global [%0], [%1], 16;" :: "r"(dst), "l"(src) : "memory");
}
#define CP_COMMIT() asm volatile("cp.async.commit_group;" ::: "memory")
#define CP_WAIT0()  asm volatile("cp.async.wait_group 0;" ::: "memory")

// ---------------------------------------------------------------------------
// Kernel 1: zero scratch, ||w||^2, build w' = -2w bf16 hi/lo (code-major)
// ---------------------------------------------------------------------------
__global__ void vq_init(const float* __restrict__ w) {
    int gid = blockIdx.x * blockDim.x + threadIdx.x;
    if (gid < NEMB * DIMV) g_embed_sum[gid] = 0.0f;
    if (gid < NEMB) {
        int j = gid;
        float s = 0.0f;
#pragma unroll
        for (int k = 0; k < DIMV; k++) {
            float v = w[k * NEMB + j];            // coalesced over j
            s = fmaf(v, v, s);
            float m = -2.0f * v;
            unsigned h = bfbits(m);
            float r = m - bflo(h);
            g_w_hi[j * DIMV + k] = (unsigned short)h;
            g_w_lo[j * DIMV + k] = (unsigned short)bfbits(r);
        }
        g_wsq[j] = s;
        g_counts[j] = 0.0f;
    }
    if (gid == 0) g_loss_sum = 0.0f;
}

// ---------------------------------------------------------------------------
// Kernel 2: persistent main — bf16-split HMMA (pass-major, dep-free) + argmin
// ---------------------------------------------------------------------------
__global__ __launch_bounds__(TPB, 1)
void vq_main(const float* __restrict__ inp, int nrows) {
    extern __shared__ __align__(1024) char sm[];
    const unsigned sbase = smem_u32(sm);
    const int tid  = threadIdx.x;
    const int lane = tid & 31;
    const int wid  = tid >> 5;

    float* swsq  = (float*)(sm + SWSQ_OFF);
    float* scnt  = (float*)(sm + SCNT_OFF);
    float* sxsq  = (float*)(sm + SXSQ_OFF);
    int*   sj    = (int*)(sm + SJ_OFF);
    float* sloss = (float*)(sm + SLOSS_OFF);

    // --- stage B (w' hi/lo) into padded rows + swsq + zero counters ---
    {
        const uint4* srcH = (const uint4*)g_w_hi;
        const uint4* srcL = (const uint4*)g_w_lo;
#pragma unroll
        for (int i = 0; i < 32; i++) {
            int idx = tid + i * TPB;        // 0..4095 : 16B chunk index
            int row = idx >> 3, c = idx & 7;
            *(uint4*)(sm + B_HI_OFF + row * ROWB + c * 16) = srcH[idx];
            *(uint4*)(sm + B_LO_OFF + row * ROWB + c * 16) = srcL[idx];
        }
        for (int j = tid; j < NEMB; j += TPB) { swsq[j] = g_wsq[j]; scnt[j] = 0.0f; }
        if (tid == 0) *sloss = 0.0f;
    }

    // lane-fixed ldmatrix address offsets
    const unsigned aoff = (unsigned)((lane & 15) * ROWB + (lane >> 4) * 16);
    const unsigned boff = (unsigned)(((lane & 7) + ((lane >> 4) << 3)) * ROWB + ((lane >> 3) & 1) * 16);
    const unsigned aHbase = sbase + A_HI_OFF + (unsigned)(wid * 32 * ROWB) + aoff;
    const unsigned aLbase = sbase + A_LO_OFF + (unsigned)(wid * 32 * ROWB) + aoff;
    const unsigned bHbase = sbase + B_HI_OFF + boff;
    const unsigned bLbase = sbase + B_LO_OFF + boff;

    float loss_acc = 0.0f;
    const int nchunks = nrows / TILE_M;

    // ---- prefetch first tile into staging ----
    {
        const float4* src = (const float4*)inp + (size_t)blockIdx.x * (TILE_M * DIMV / 4);
#pragma unroll
        for (int i = 0; i < 16; i++) {
            int idx = tid + (i << 7);
            cp_async16(sbase + STAGE_OFF + idx * 16, src + idx);
        }
        CP_COMMIT();
    }

    for (int tile = blockIdx.x; tile < nchunks; tile += gridDim.x) {
        CP_WAIT0();
        __syncthreads();   // staging visible to all; prev scatter done (A reusable)

        // ---- convert x tile from staging (smem) ----
        const float4* stg = (const float4*)(sm + STAGE_OFF);
#pragma unroll
        for (int i = 0; i < 16; i++) {
            int idx = tid + (i << 7);
            float4 v = stg[idx];
            unsigned h0 = bfbits(v.x), h1 = bfbits(v.y), h2 = bfbits(v.z), h3 = bfbits(v.w);
            unsigned l0 = bfbits(v.x - bflo(h0)), l1 = bfbits(v.y - bflo(h1));
            unsigned l2 = bfbits(v.z - bflo(h2)), l3 = bfbits(v.w - bflo(h3));
            unsigned long long hw = ((unsigned long long)(h2 | (h3 << 16)) << 32) | (h0 | (h1 << 16));
            unsigned long long lw = ((unsigned long long)(l2 | (l3 << 16)) << 32) | (l0 | (l1 << 16));
            int row = idx >> 4, kc = idx & 15;
            *(unsigned long long*)(sm + A_HI_OFF + row * ROWB + kc * 8) = hw;
            *(unsigned long long*)(sm + A_LO_OFF + row * ROWB + kc * 8) = lw;
            float pq = fmaf(v.x, v.x, fmaf(v.y, v.y, fmaf(v.z, v.z, v.w * v.w)));
#pragma unroll
            for (int m = 1; m < 16; m <<= 1) pq += __shfl_xor_sync(0xFFFFFFFFu, pq, m);
            if ((lane & 15) == 0) sxsq[(i << 3) + (tid >> 4)] = pq;
        }
        __syncthreads();   // S2: A smem + sxsq ready; staging reads done

        // ---- issue prefetch of next tile (overlaps with MMA) ----
        {
            int nxt = tile + gridDim.x;
            if (nxt < nchunks) {
                const float4* src = (const float4*)inp + (size_t)nxt * (TILE_M * DIMV / 4);
#pragma unroll
                for (int i = 0; i < 16; i++) {
                    int idx = tid + (i << 7);
                    cp_async16(sbase + STAGE_OFF + idx * 16, src + idx);
                }
            }
            CP_COMMIT();
        }

        // ---- load A fragments (resident for whole tile) ----
        unsigned Ah[2][4][4], Al[2][4][4];
#pragma unroll
        for (int mt = 0; mt < 2; mt++)
#pragma unroll
            for (int ks = 0; ks < 4; ks++) {
                unsigned ao = (unsigned)(mt * 16 * ROWB + ks * 32);
                ldm_x4(Ah[mt][ks][0], Ah[mt][ks][1], Ah[mt][ks][2], Ah[mt][ks][3], aHbase + ao);
                ldm_x4(Al[mt][ks][0], Al[mt][ks][1], Al[mt][ks][2], Al[mt][ks][3], aLbase + ao);
            }

        float bst[4] = {__int_as_float(0x7F800000), __int_as_float(0x7F800000),
                        __int_as_float(0x7F800000), __int_as_float(0x7F800000)};
        int   bj[4]  = {0, 0, 0, 0};

        for (int chunk = 0; chunk < 8; chunk++) {
            float acc[2][8][4];
#pragma unroll
            for (int mt = 0; mt < 2; mt++)
#pragma unroll
                for (int nt = 0; nt < 8; nt++)
#pragma unroll
                    for (int q = 0; q < 4; q++) acc[mt][nt][q] = 0.0f;

            unsigned bc = (unsigned)(chunk * 64 * ROWB);
#pragma unroll
            for (int ks = 0; ks < 4; ks++) {
                // load all B fragments for this k-step first (8 ldmatrix, MLP)
                unsigned Bh[4][4], Bl[4][4];
#pragma unroll
                for (int pr = 0; pr < 4; pr++) {
                    unsigned off = bc + (unsigned)(pr * 16 * ROWB + ks * 32);
                    ldm_x4(Bh[pr][0], Bh[pr][1], Bh[pr][2], Bh[pr][3], bHbase + off);
                    ldm_x4(Bl[pr][0], Bl[pr][1], Bl[pr][2], Bl[pr][3], bLbase + off);
                }
                // pass-major sweeps: 16 independent acc quads per sweep
#pragma unroll
                for (int pr = 0; pr < 4; pr++)
#pragma unroll
                    for (int mt = 0; mt < 2; mt++) {
                        mma_bf16(acc[mt][2*pr],   Ah[mt][ks], Bh[pr][0], Bh[pr][1]);
                        mma_bf16(acc[mt][2*pr+1], Ah[mt][ks], Bh[pr][2], Bh[pr][3]);
                    }
#pragma unroll
                for (int pr = 0; pr < 4; pr++)
#pragma unroll
                    for (int mt = 0; mt < 2; mt++) {
                        mma_bf16(acc[mt][2*pr],   Ah[mt][ks], Bl[pr][0], Bl[pr][1]);
                        mma_bf16(acc[mt][2*pr+1], Ah[mt][ks], Bl[pr][2], Bl[pr][3]);
                    }
#pragma unroll
                for (int pr = 0; pr < 4; pr++)
#pragma unroll
                    for (int mt = 0; mt < 2; mt++) {
                        mma_bf16(acc[mt][2*pr],   Al[mt][ks], Bh[pr][0], Bh[pr][1]);
                        mma_bf16(acc[mt][2*pr+1], Al[mt][ks], Bh[pr][2], Bh[pr][3]);
                    }
            }

            // ---- fold into per-row running argmin (ascending j scan) ----
#pragma unroll
            for (int nt = 0; nt < 8; nt++) {
                int jb = chunk * 64 + nt * 8 + (lane & 3) * 2;
                float2 wq = *(float2*)(swsq + jb);
#pragma unroll
                for (int mt = 0; mt < 2; mt++) {
                    float s0 = acc[mt][nt][0] + wq.x;
                    float s1 = acc[mt][nt][1] + wq.y;
                    float s2 = acc[mt][nt][2] + wq.x;
                    float s3 = acc[mt][nt][3] + wq.y;
                    int slo = mt * 2, shi = mt * 2 + 1;
                    if (s0 < bst[slo]) { bst[slo] = s0; bj[slo] = jb; }
                    if (s1 < bst[slo]) { bst[slo] = s1; bj[slo] = jb + 1; }
                    if (s2 < bst[shi]) { bst[shi] = s2; bj[shi] = jb; }
                    if (s3 < bst[shi]) { bst[shi] = s3; bj[shi] = jb + 1; }
                }
            }
        }

        // ---- quad-reduce (val, idx) lexicographic; owners record results ----
#pragma unroll
        for (int s = 0; s < 4; s++) {
            float b = bst[s]; int j = bj[s];
#pragma unroll
            for (int off = 1; off <= 2; off <<= 1) {
                float ob = __shfl_xor_sync(0xFFFFFFFFu, b, off);
                int   oj = __shfl_xor_sync(0xFFFFFFFFu, j, off);
                if (ob < b || (ob == b && oj < j)) { b = ob; j = oj; }
            }
            if ((lane & 3) == 0) {
                int r = wid * 32 + (s >> 1) * 16 + (lane >> 2) + (s & 1) * 8;
                sj[r] = j;
                loss_acc += b + sxsq[r];
                atomicAdd(&scnt[j], 1.0f);
            }
        }
        __syncthreads();   // S3: sj complete

        // ---- embed_sum scatter: one row per thread, v4 global reductions ----
        {
            int j = sj[tid];
            float* dst = g_embed_sum + j * DIMV;
            const char* hrow = sm + A_HI_OFF + tid * ROWB;
            const char* lrow = sm + A_LO_OFF + tid * ROWB;
#pragma unroll
            for (int c = 0; c < 8; c++) {
                uint4 h = *(const uint4*)(hrow + c * 16);
                uint4 l = *(const uint4*)(lrow + c * 16);
                float f0 = bflo(h.x) + bflo(l.x), f1 = bfhi(h.x) + bfhi(l.x);
                float f2 = bflo(h.y) + bflo(l.y), f3 = bfhi(h.y) + bfhi(l.y);
                float f4 = bflo(h.z) + bflo(l.z), f5 = bfhi(h.z) + bfhi(l.z);
                float f6 = bflo(h.w) + bflo(l.w), f7 = bfhi(h.w) + bfhi(l.w);
                red_add_v4(dst + c * 8,     f0, f1, f2, f3);
                red_add_v4(dst + c * 8 + 4, f4, f5, f6, f7);
            }
        }
    }

    // ---- flush block-local accumulators ----
    atomicAdd(sloss, loss_acc);
    __syncthreads();
    for (int j = tid; j < NEMB; j += TPB)
        if (scnt[j] != 0.0f) atomicAdd(&g_counts[j], scnt[j]);
    if (tid == 0) atomicAdd(&g_loss_sum, *sloss);
}

// ---------------------------------------------------------------------------
// Kernel 3a: scalar reductions — n, per-code inv factor, loss, perplexity, cs
// ---------------------------------------------------------------------------
__global__ void vq_final1(const float* __restrict__ cs_in,
                          float* __restrict__ out, int nrows) {
    __shared__ float red[NEMB];
    int j = threadIdx.x;

    float counts = g_counts[j];
    float ncs = fmaf(0.99f, cs_in[j], 0.01f * counts);

    red[j] = ncs;
    __syncthreads();
#pragma unroll
    for (int off = NEMB / 2; off; off >>= 1) {
        if (j < off) red[j] += red[j + off];
        __syncthreads();
    }
    float n = red[0];
    __syncthreads();

    float csj = (ncs + 1e-5f) / (n + (float)NEMB * 1e-5f) * n;
    g_inv[j] = 1.0f / csj;
    out[2 + DIMV * NEMB + j] = ncs;  // new_cluster_size

    float p = counts / (float)nrows;
    red[j] = p * logf(p + 1e-10f);
    __syncthreads();
#pragma unroll
    for (int off = NEMB / 2; off; off >>= 1) {
        if (j < off) red[j] += red[j + off];
        __syncthreads();
    }
    if (j == 0) {
        out[1] = expf(-red[0]);
        out[0] = 0.25f * g_loss_sum / ((float)nrows * (float)DIMV);
    }
}

// ---------------------------------------------------------------------------
// Kernel 3b: parallel output writer — new_embed_avg + new_w (256KB of stores)
// ---------------------------------------------------------------------------
__global__ void vq_final2(const float* __restrict__ ea_in, float* __restrict__ out) {
    int gid = blockIdx.x * blockDim.x + threadIdx.x;   // 0 .. 32767
    int k = gid >> 9, j = gid & (NEMB - 1);
    float ea = fmaf(0.99f, ea_in[gid], 0.01f * g_embed_sum[j * DIMV + k]);
    const int EA_OFF = 2 + DIMV * NEMB + NEMB;
    out[EA_OFF + gid] = ea;              // new_embed_avg
    out[2 + gid] = ea * g_inv[j];        // new_w
}

// ---------------------------------------------------------------------------
extern "C" void kernel_launch(void* const* d_in, const int* in_sizes, int n_in,
                              void* d_out, int out_size) {
    const float* inp = (const float*)d_in[0];
    const float* w   = (const float*)d_in[1];
    const float* cs  = (const float*)d_in[2];
    const float* ea  = (const float*)d_in[3];
    int nrows = in_sizes[0] / DIMV;

    cudaFuncSetAttribute(vq_main, cudaFuncAttributeMaxDynamicSharedMemorySize, SMEM_BYTES);

    vq_init<<<64, 512>>>(w);
    vq_main<<<148, TPB, SMEM_BYTES>>>(inp, nrows);
    vq_final1<<<1, NEMB>>>(cs, (float*)d_out, nrows);
    vq_final2<<<DIMV * NEMB / 256, 256>>>(ea, (float*)d_out);
}

// round 6
// speedup vs baseline: 3.5617x; 1.0892x over previous
#include <cuda_runtime.h>
#include <cuda_bf16.h>
#include <math.h>

#define DIMV   64
#define NEMB   512
#define TPB    512
#define TILE_M 128
#define ROWB   144          // padded row stride: 72 bf16 (conflict-free ldmatrix)

// ---------------- smem layout (bytes) ----------------
#define B_HI_OFF   0                          // 512 x 144B
#define B_LO_OFF   (512*ROWB)                 // 73728
#define A_HI_OFF   (2*512*ROWB)               // 147456, 128 x 144B
#define A_LO_OFF   (A_HI_OFF + 128*ROWB)      // 165888
#define STAGE_OFF  (A_LO_OFF + 128*ROWB)      // 184320, raw fp32 tile 32KB
#define SWSQ_OFF   (STAGE_OFF + 32768)        // 217088, 512 f32
#define SCNT_OFF   (SWSQ_OFF + 2048)          // 512 f32
#define SXSQ_OFF   (SCNT_OFF + 2048)          // 128 f32
#define SVAL_OFF   (SXSQ_OFF + 512)           // 2 x 128 f32 (per-half argmin val)
#define SJI_OFF    (SVAL_OFF + 1024)          // 2 x 128 i32 (per-half argmin idx)
#define SJ_OFF     (SJI_OFF + 1024)           // 128 i32 final
#define SLOSS_OFF  (SJ_OFF + 512)
#define SMEM_BYTES (SLOSS_OFF + 16)           // 224272

// ---------------- device scratch ----------------
__device__ float          g_wsq[NEMB];
__device__ unsigned short g_w_hi[NEMB * DIMV];   // [j][k], w' = -2w, bf16 hi
__device__ unsigned short g_w_lo[NEMB * DIMV];   // bf16 residual
__device__ __align__(16) float g_embed_sum[NEMB * DIMV];  // code-major [j][k]
__device__ float          g_counts[NEMB];
__device__ float          g_inv[NEMB];
__device__ float          g_loss_sum;

// ---------------- helpers ----------------
__device__ __forceinline__ unsigned smem_u32(const void* p) {
    unsigned a;
    asm("{ .reg .u64 t; cvta.to.shared.u64 t, %1; cvt.u32.u64 %0, t; }" : "=r"(a) : "l"(p));
    return a;
}
__device__ __forceinline__ unsigned bfbits(float f) {
    return (unsigned)__bfloat16_as_ushort(__float2bfloat16(f));
}
__device__ __forceinline__ float bflo(unsigned u) { return __uint_as_float(u << 16); }
__device__ __forceinline__ float bfhi(unsigned u) { return __uint_as_float(u & 0xFFFF0000u); }

__device__ __forceinline__ void ldm_x4(unsigned &r0, unsigned &r1, unsigned &r2, unsigned &r3,
                                       unsigned addr) {
    asm volatile("ldmatrix.sync.aligned.m8n8.x4.shared.b16 {%0,%1,%2,%3}, [%4];"
                 : "=r"(r0), "=r"(r1), "=r"(r2), "=r"(r3) : "r"(addr));
}
__device__ __forceinline__ void mma_bf16(float* d, const unsigned* a, unsigned b0, unsigned b1) {
    asm volatile("mma.sync.aligned.m16n8k16.row.col.f32.bf16.bf16.f32 "
                 "{%0,%1,%2,%3},{%4,%5,%6,%7},{%8,%9},{%0,%1,%2,%3};"
                 : "+f"(d[0]), "+f"(d[1]), "+f"(d[2]), "+f"(d[3])
                 : "r"(a[0]), "r"(a[1]), "r"(a[2]), "r"(a[3]), "r"(b0), "r"(b1));
}
__device__ __forceinline__ void red_add_v4(float* p, float a, float b, float c, float d) {
    asm volatile("red.global.add.v4.f32 [%0], {%1,%2,%3,%4};"
                 :: "l"(p), "f"(a), "f"(b), "f"(c), "f"(d) : "memory");
}
__device__ __forceinline__ void cp_async16(unsigned dst, const void* src) {
    asm volatile("cp.async.cg.shared.global [%0], [%1], 16;" :: "r"(dst), "l"(src) : "memory");
}
#define CP_COMMIT() asm volatile("cp.async.commit_group;" ::: "memory")
#define CP_WAIT0()  asm volatile("cp.async.wait_group 0;" ::: "memory")

// ---------------------------------------------------------------------------
// Kernel 1: zero scratch, ||w||^2, build w' = -2w bf16 hi/lo (code-major)
// ---------------------------------------------------------------------------
__global__ void vq_init(const float* __restrict__ w) {
    int gid = blockIdx.x * blockDim.x + threadIdx.x;
    if (gid < NEMB * DIMV) g_embed_sum[gid] = 0.0f;
    if (gid < NEMB) {
        int j = gid;
        float s = 0.0f;
#pragma unroll
        for (int k = 0; k < DIMV; k++) {
            float v = w[k * NEMB + j];            // coalesced over j
            s = fmaf(v, v, s);
            float m = -2.0f * v;
            unsigned h = bfbits(m);
            float r = m - bflo(h);
            g_w_hi[j * DIMV + k] = (unsigned short)h;
            g_w_lo[j * DIMV + k] = (unsigned short)bfbits(r);
        }
        g_wsq[j] = s;
        g_counts[j] = 0.0f;
    }
    if (gid == 0) g_loss_sum = 0.0f;
}

// ---------------------------------------------------------------------------
// Kernel 2: persistent main — 16 warps (4/SMSP), M x N warp split, HMMA
// ---------------------------------------------------------------------------
__global__ __launch_bounds__(TPB, 1)
void vq_main(const float* __restrict__ inp, int nrows) {
    extern __shared__ __align__(1024) char sm[];
    const unsigned sbase = smem_u32(sm);
    const int tid  = threadIdx.x;
    const int lane = tid & 31;
    const int wid  = tid >> 5;
    const int mgrp = wid >> 1;      // 0..7 : row group of 16
    const int nh   = wid & 1;       // 0..1 : code half of 256

    float* swsq  = (float*)(sm + SWSQ_OFF);
    float* scnt  = (float*)(sm + SCNT_OFF);
    float* sxsq  = (float*)(sm + SXSQ_OFF);
    float* sval  = (float*)(sm + SVAL_OFF);
    int*   sji   = (int*)(sm + SJI_OFF);
    int*   sj    = (int*)(sm + SJ_OFF);
    float* sloss = (float*)(sm + SLOSS_OFF);

    // --- stage B (w' hi/lo) into padded rows + swsq + zero counters ---
    {
        const uint4* srcH = (const uint4*)g_w_hi;
        const uint4* srcL = (const uint4*)g_w_lo;
#pragma unroll
        for (int i = 0; i < 8; i++) {
            int idx = tid + i * TPB;        // 0..4095 : 16B chunk index
            int row = idx >> 3, c = idx & 7;
            *(uint4*)(sm + B_HI_OFF + row * ROWB + c * 16) = srcH[idx];
            *(uint4*)(sm + B_LO_OFF + row * ROWB + c * 16) = srcL[idx];
        }
        swsq[tid] = g_wsq[tid];
        scnt[tid] = 0.0f;
        if (tid == 0) *sloss = 0.0f;
    }

    // lane-fixed ldmatrix address offsets
    const unsigned aoff = (unsigned)((lane & 15) * ROWB + (lane >> 4) * 16);
    const unsigned boff = (unsigned)(((lane & 7) + ((lane >> 4) << 3)) * ROWB + ((lane >> 3) & 1) * 16);
    const unsigned aHbase = sbase + A_HI_OFF + (unsigned)(mgrp * 16 * ROWB) + aoff;
    const unsigned aLbase = sbase + A_LO_OFF + (unsigned)(mgrp * 16 * ROWB) + aoff;
    const unsigned bHbase = sbase + B_HI_OFF + (unsigned)(nh * 256 * ROWB) + boff;
    const unsigned bLbase = sbase + B_LO_OFF + (unsigned)(nh * 256 * ROWB) + boff;

    float loss_acc = 0.0f;
    const int nchunks = nrows / TILE_M;

    // ---- prefetch first tile into staging ----
    {
        const float4* src = (const float4*)inp + (size_t)blockIdx.x * (TILE_M * DIMV / 4);
#pragma unroll
        for (int i = 0; i < 4; i++) {
            int idx = tid + i * TPB;
            cp_async16(sbase + STAGE_OFF + idx * 16, src + idx);
        }
        CP_COMMIT();
    }

    for (int tile = blockIdx.x; tile < nchunks; tile += gridDim.x) {
        CP_WAIT0();
        __syncthreads();   // S1: staging visible; prev scatter done (A reusable)

        // ---- convert x tile from staging (smem) ----
        const float4* stg = (const float4*)(sm + STAGE_OFF);
#pragma unroll
        for (int i = 0; i < 4; i++) {
            int idx = tid + i * TPB;
            float4 v = stg[idx];
            unsigned h0 = bfbits(v.x), h1 = bfbits(v.y), h2 = bfbits(v.z), h3 = bfbits(v.w);
            unsigned l0 = bfbits(v.x - bflo(h0)), l1 = bfbits(v.y - bflo(h1));
            unsigned l2 = bfbits(v.z - bflo(h2)), l3 = bfbits(v.w - bflo(h3));
            unsigned long long hw = ((unsigned long long)(h2 | (h3 << 16)) << 32) | (h0 | (h1 << 16));
            unsigned long long lw = ((unsigned long long)(l2 | (l3 << 16)) << 32) | (l0 | (l1 << 16));
            int row = idx >> 4, kc = idx & 15;
            *(unsigned long long*)(sm + A_HI_OFF + row * ROWB + kc * 8) = hw;
            *(unsigned long long*)(sm + A_LO_OFF + row * ROWB + kc * 8) = lw;
            float pq = fmaf(v.x, v.x, fmaf(v.y, v.y, fmaf(v.z, v.z, v.w * v.w)));
#pragma unroll
            for (int m = 1; m < 16; m <<= 1) pq += __shfl_xor_sync(0xFFFFFFFFu, pq, m);
            if ((lane & 15) == 0) sxsq[row] = pq;
        }
        __syncthreads();   // S2: A smem + sxsq ready; staging reads done

        // ---- issue prefetch of next tile (overlaps with MMA) ----
        {
            int nxt = tile + gridDim.x;
            if (nxt < nchunks) {
                const float4* src = (const float4*)inp + (size_t)nxt * (TILE_M * DIMV / 4);
#pragma unroll
                for (int i = 0; i < 4; i++) {
                    int idx = tid + i * TPB;
                    cp_async16(sbase + STAGE_OFF + idx * 16, src + idx);
                }
            }
            CP_COMMIT();
        }

        // ---- load A fragments (resident for whole tile) ----
        unsigned Ah[4][4], Al[4][4];
#pragma unroll
        for (int ks = 0; ks < 4; ks++) {
            unsigned ao = (unsigned)(ks * 32);
            ldm_x4(Ah[ks][0], Ah[ks][1], Ah[ks][2], Ah[ks][3], aHbase + ao);
            ldm_x4(Al[ks][0], Al[ks][1], Al[ks][2], Al[ks][3], aLbase + ao);
        }

        float bst[2] = {__int_as_float(0x7F800000), __int_as_float(0x7F800000)};
        int   bj[2]  = {0, 0};

#pragma unroll
        for (int chunk = 0; chunk < 4; chunk++) {
            // init acc with ||w||^2 folded in (C operand of first MMA)
            float acc[8][4];
            int jb0 = nh * 256 + chunk * 64 + (lane & 3) * 2;
#pragma unroll
            for (int nt = 0; nt < 8; nt++) {
                float2 wq = *(float2*)(swsq + jb0 + nt * 8);
                acc[nt][0] = wq.x; acc[nt][1] = wq.y;
                acc[nt][2] = wq.x; acc[nt][3] = wq.y;
            }

            unsigned bc = (unsigned)(chunk * 64 * ROWB);
#pragma unroll
            for (int ks = 0; ks < 4; ks++) {
                unsigned B0[4][4];
#pragma unroll
                for (int pr = 0; pr < 4; pr++) {
                    unsigned off = bc + (unsigned)(pr * 16 * ROWB + ks * 32);
                    ldm_x4(B0[pr][0], B0[pr][1], B0[pr][2], B0[pr][3], bHbase + off);
                }
                // pass 1: Ah x Bh
#pragma unroll
                for (int pr = 0; pr < 4; pr++) {
                    mma_bf16(acc[2*pr],   Ah[ks], B0[pr][0], B0[pr][1]);
                    mma_bf16(acc[2*pr+1], Ah[ks], B0[pr][2], B0[pr][3]);
                }
                // pass 2: Al x Bh (reuses B0)
#pragma unroll
                for (int pr = 0; pr < 4; pr++) {
                    mma_bf16(acc[2*pr],   Al[ks], B0[pr][0], B0[pr][1]);
                    mma_bf16(acc[2*pr+1], Al[ks], B0[pr][2], B0[pr][3]);
                }
                // pass 3: Ah x Bl (overwrite B0 with Bl)
#pragma unroll
                for (int pr = 0; pr < 4; pr++) {
                    unsigned off = bc + (unsigned)(pr * 16 * ROWB + ks * 32);
                    ldm_x4(B0[pr][0], B0[pr][1], B0[pr][2], B0[pr][3], bLbase + off);
                }
#pragma unroll
                for (int pr = 0; pr < 4; pr++) {
                    mma_bf16(acc[2*pr],   Ah[ks], B0[pr][0], B0[pr][1]);
                    mma_bf16(acc[2*pr+1], Ah[ks], B0[pr][2], B0[pr][3]);
                }
            }

            // ---- fold into per-slot running argmin (ascending j scan) ----
#pragma unroll
            for (int nt = 0; nt < 8; nt++) {
                int jb = jb0 + nt * 8;
                float s0 = acc[nt][0], s1 = acc[nt][1];
                float s2 = acc[nt][2], s3 = acc[nt][3];
                if (s0 < bst[0]) { bst[0] = s0; bj[0] = jb; }
                if (s1 < bst[0]) { bst[0] = s1; bj[0] = jb + 1; }
                if (s2 < bst[1]) { bst[1] = s2; bj[1] = jb; }
                if (s3 < bst[1]) { bst[1] = s3; bj[1] = jb + 1; }
            }
        }

        // ---- quad-reduce (val, idx) lexicographic; owners write per-half ----
#pragma unroll
        for (int s = 0; s < 2; s++) {
            float b = bst[s]; int j = bj[s];
#pragma unroll
            for (int off = 1; off <= 2; off <<= 1) {
                float ob = __shfl_xor_sync(0xFFFFFFFFu, b, off);
                int   oj = __shfl_xor_sync(0xFFFFFFFFu, j, off);
                if (ob < b || (ob == b && oj < j)) { b = ob; j = oj; }
            }
            if ((lane & 3) == 0) {
                int r = mgrp * 16 + (lane >> 2) + s * 8;
                sval[nh * 128 + r] = b;
                sji[nh * 128 + r] = j;
            }
        }
        __syncthreads();   // S3: both halves' candidates in smem

        // ---- combine halves, record winner, loss, counts ----
        if (tid < TILE_M) {
            int r = tid;
            float v0 = sval[r], v1 = sval[128 + r];
            int   j0 = sji[r],  j1 = sji[128 + r];
            int   jw = (v1 < v0) ? j1 : j0;      // tie -> lower half (lower j)
            float vw = (v1 < v0) ? v1 : v0;
            sj[r] = jw;
            loss_acc += vw + sxsq[r];
            atomicAdd(&scnt[jw], 1.0f);
        }
        __syncthreads();   // S4: sj complete

        // ---- embed_sum scatter: 4 threads per row, v4 global reductions ----
        {
            int r = tid >> 2, part = tid & 3;
            int j = sj[r];
            float* dst = g_embed_sum + j * DIMV + part * 16;
            const char* hrow = sm + A_HI_OFF + r * ROWB + part * 32;
            const char* lrow = sm + A_LO_OFF + r * ROWB + part * 32;
#pragma unroll
            for (int c = 0; c < 2; c++) {
                uint4 h = *(const uint4*)(hrow + c * 16);
                uint4 l = *(const uint4*)(lrow + c * 16);
                float f0 = bflo(h.x) + bflo(l.x), f1 = bfhi(h.x) + bfhi(l.x);
                float f2 = bflo(h.y) + bflo(l.y), f3 = bfhi(h.y) + bfhi(l.y);
                float f4 = bflo(h.z) + bflo(l.z), f5 = bfhi(h.z) + bfhi(l.z);
                float f6 = bflo(h.w) + bflo(l.w), f7 = bfhi(h.w) + bfhi(l.w);
                red_add_v4(dst + c * 8,     f0, f1, f2, f3);
                red_add_v4(dst + c * 8 + 4, f4, f5, f6, f7);
            }
        }
    }

    // ---- flush block-local accumulators ----
    atomicAdd(sloss, loss_acc);
    __syncthreads();
    if (scnt[tid] != 0.0f) atomicAdd(&g_counts[tid], scnt[tid]);
    if (tid == 0) atomicAdd(&g_loss_sum, *sloss);
}

// ---------------------------------------------------------------------------
// Kernel 3a: scalar reductions — n, per-code inv factor, loss, perplexity, cs
// ---------------------------------------------------------------------------
__global__ void vq_final1(const float* __restrict__ cs_in,
                          float* __restrict__ out, int nrows) {
    __shared__ float red[NEMB];
    int j = threadIdx.x;

    float counts = g_counts[j];
    float ncs = fmaf(0.99f, cs_in[j], 0.01f * counts);

    red[j] = ncs;
    __syncthreads();
#pragma unroll
    for (int off = NEMB / 2; off; off >>= 1) {
        if (j < off) red[j] += red[j + off];
        __syncthreads();
    }
    float n = red[0];
    __syncthreads();

    float csj = (ncs + 1e-5f) / (n + (float)NEMB * 1e-5f) * n;
    g_inv[j] = 1.0f / csj;
    out[2 + DIMV * NEMB + j] = ncs;  // new_cluster_size

    float p = counts / (float)nrows;
    red[j] = p * logf(p + 1e-10f);
    __syncthreads();
#pragma unroll
    for (int off = NEMB / 2; off; off >>= 1) {
        if (j < off) red[j] += red[j + off];
        __syncthreads();
    }
    if (j == 0) {
        out[1] = expf(-red[0]);
        out[0] = 0.25f * g_loss_sum / ((float)nrows * (float)DIMV);
    }
}

// ---------------------------------------------------------------------------
// Kernel 3b: parallel output writer — new_embed_avg + new_w (256KB of stores)
// ---------------------------------------------------------------------------
__global__ void vq_final2(const float* __restrict__ ea_in, float* __restrict__ out) {
    int gid = blockIdx.x * blockDim.x + threadIdx.x;   // 0 .. 32767
    int k = gid >> 9, j = gid & (NEMB - 1);
    float ea = fmaf(0.99f, ea_in[gid], 0.01f * g_embed_sum[j * DIMV + k]);
    const int EA_OFF = 2 + DIMV * NEMB + NEMB;
    out[EA_OFF + gid] = ea;              // new_embed_avg
    out[2 + gid] = ea * g_inv[j];        // new_w
}

// ---------------------------------------------------------------------------
extern "C" void kernel_launch(void* const* d_in, const int* in_sizes, int n_in,
                              void* d_out, int out_size) {
    const float* inp = (const float*)d_in[0];
    const float* w   = (const float*)d_in[1];
    const float* cs  = (const float*)d_in[2];
    const float* ea  = (const float*)d_in[3];
    int nrows = in_sizes[0] / DIMV;

    cudaFuncSetAttribute(vq_main, cudaFuncAttributeMaxDynamicSharedMemorySize, SMEM_BYTES);

    vq_init<<<64, 512>>>(w);
    vq_main<<<148, TPB, SMEM_BYTES>>>(inp, nrows);
    vq_final1<<<1, NEMB>>>(cs, (float*)d_out, nrows);
    vq_final2<<<DIMV * NEMB / 256, 256>>>(ea, (float*)d_out);
}